// round 13
// baseline (speedup 1.0000x reference)
#include <cuda_runtime.h>
#include <cuda_fp16.h>
#include <math.h>
#include <stdint.h>

// ---------------- problem constants ----------------
#define SEQ   4096
#define HID   2048
#define NH    16
#define NKV   4
#define DH    128
#define BLKQ  64
#define NBLK  64
#define MSK   32
#define KTOP  8
#define QKVN  3072          // fused QKV output columns (2048 q | 512 k | 512 v)

#define NEGV  (-1000000000.0f)

// ---------------- scratch (device globals; no allocation allowed) ----------------
__device__ float  g_qkv[SEQ * QKVN];         // fused q|k|v fp32, layout [s][3072]
__device__ __half g_ha_hi[SEQ * HID];        // hidden_states hi plane [s][k]
__device__ __half g_ha_lo[SEQ * HID];        // hidden_states lo plane
__device__ __half g_wb_hi[QKVN * HID];       // packed W_qkv hi, [n][k] row-major
__device__ __half g_wb_lo[QKVN * HID];
__device__ __half g_oa_hi[SEQ * HID];        // attention-out hi plane [s][k]
__device__ __half g_oa_lo[SEQ * HID];
__device__ __half g_wob_hi[HID * HID];       // Wo hi, [n][k] row-major
__device__ __half g_wob_lo[HID * HID];
__device__ float  g_Sq[NH * NBLK * MSK];
__device__ float  g_Sk[NKV * NBLK * MSK];
__device__ int    g_topk[NH * NBLK * KTOP];
__device__ float  g_cos[SEQ * 64];
__device__ float  g_sin[SEQ * 64];
__device__ double g_invf[64];

// ---------------- common fp16 helpers ----------------
__device__ __forceinline__ uint32_t smem_u32(const void* p) {
    uint32_t a;
    asm("{ .reg .u64 t; cvta.to.shared.u64 t, %1; cvt.u32.u64 %0, t; }" : "=r"(a) : "l"(p));
    return a;
}
__device__ __forceinline__ void mma16816(float c[4],
    uint32_t a0, uint32_t a1, uint32_t a2, uint32_t a3, uint32_t b0, uint32_t b1)
{
    asm volatile(
        "mma.sync.aligned.m16n8k16.row.col.f32.f16.f16.f32 "
        "{%0,%1,%2,%3}, {%4,%5,%6,%7}, {%8,%9}, {%0,%1,%2,%3};"
        : "+f"(c[0]), "+f"(c[1]), "+f"(c[2]), "+f"(c[3])
        : "r"(a0), "r"(a1), "r"(a2), "r"(a3), "r"(b0), "r"(b1));
}
__device__ __forceinline__ void split2(float x, float y, uint32_t& H, uint32_t& L) {
    __half hx = __float2half_rn(x), hy = __float2half_rn(y);
    __half2 hh = __halves2half2(hx, hy);
    H = *(uint32_t*)&hh;
    __half2 ll = __halves2half2(__float2half_rn(x - __half2float(hx)),
                                __float2half_rn(y - __half2float(hy)));
    L = *(uint32_t*)&ll;
}
#define LDSMX4(r0, r1, r2, r3, addr) \
    asm volatile("ldmatrix.sync.aligned.m8n8.x4.shared.b16 {%0,%1,%2,%3}, [%4];" \
                 : "=r"(r0), "=r"(r1), "=r"(r2), "=r"(r3) : "r"(addr))

#define CP16(dst, src) \
    asm volatile("cp.async.cg.shared.global [%0], [%1], 16;" :: "r"(dst), "l"(src))
#define CP_COMMIT() asm volatile("cp.async.commit_group;")
#define CP_WAIT1()  asm volatile("cp.async.wait_group 1;")

// =======================================================================
// fp16 split GEMM v2 (3-pass, ldmatrix): C[M,N] = A[M,K] @ B^T
// A planes row-major [M][K]; B planes row-major [N][K].
// CTA 128x128, BK=32, 256 threads, warp tile 64x32, double-buffered cp.async.
// Passes: hh, lh (B-hi reused), hl (A-hi reused) — all fragments resident.
// =======================================================================
#define RSTR 20                      // words per smem row (40 halfs, 80B)
#define PLANE_W (128 * RSTR)         // 2560 words
#define STG_W   (4 * PLANE_W)        // 10240 words / stage
#define GEMM_SMEM_BYTES (2 * STG_W * 4)   // 81920 B

__global__ __launch_bounds__(256, 2) void gemm_fp16_kernel(
    const __half* __restrict__ Ah, const __half* __restrict__ Al,
    const __half* __restrict__ Bh, const __half* __restrict__ Bl,
    float* __restrict__ C, int M, int N, int K)
{
    extern __shared__ uint32_t smw[];
    const uint32_t smb = smem_u32(smw);

    const int bx = blockIdx.x * 128;    // N offset
    const int by = blockIdx.y * 128;    // M offset
    const int tid  = threadIdx.x;
    const int warp = tid >> 5;
    const int lane = tid & 31;
    const int warp_m = (warp & 1) * 64;
    const int warp_n = (warp >> 1) * 32;

    // ldmatrix lane->address mapping
    const int mat = lane >> 3, mr = lane & 7;
    const int a_row = (mat & 1) * 8 + mr;     // mats: (m0-7,k0),(m8-15,k0),(m0-7,k8),(m8-15,k8)
    const int a_kw  = (mat >> 1) * 4;         // +8 halfs = +4 words
    const int b_row = (mat >> 1) * 8 + mr;    // mats: (n0-7,k0),(n0-7,k8),(n8-15,k0),(n8-15,k8)
    const int b_kw  = (mat & 1) * 4;

    const int NIT = K / 32;
    const int lrow = tid & 127;
    const int loff = (tid >> 7) * 32;         // 0 or 32 bytes

    auto load_stage = [&](int it, int s) {
        const int kt = it * 32;
        const uint32_t base = smb + (uint32_t)s * (STG_W * 4);
        const __half* srcs[4] = {
            Ah + (size_t)(by + lrow) * K + kt,
            Al + (size_t)(by + lrow) * K + kt,
            Bh + (size_t)(bx + lrow) * K + kt,
            Bl + (size_t)(bx + lrow) * K + kt };
#pragma unroll
        for (int p = 0; p < 4; ++p) {
            uint32_t dst = base + (p * PLANE_W + lrow * RSTR) * 4 + loff;
            const char* src = (const char*)srcs[p] + loff;
            CP16(dst, src);
            CP16(dst + 16, src + 16);
        }
    };

    float acc[4][4][4];
#pragma unroll
    for (int mt = 0; mt < 4; mt++)
#pragma unroll
        for (int nt = 0; nt < 4; nt++)
#pragma unroll
            for (int r = 0; r < 4; r++) acc[mt][nt][r] = 0.0f;

    load_stage(0, 0); CP_COMMIT();
    load_stage(1, 1); CP_COMMIT();

    for (int it = 0; it < NIT; ++it) {
        CP_WAIT1();
        __syncthreads();

        const uint32_t sbase = smb + (uint32_t)(it & 1) * (STG_W * 4);
        const uint32_t AHo = sbase;
        const uint32_t ALo = sbase + PLANE_W * 4;
        const uint32_t BHo = sbase + 2 * PLANE_W * 4;
        const uint32_t BLo = sbase + 3 * PLANE_W * 4;

#pragma unroll
        for (int kk = 0; kk < 2; ++kk) {
            const uint32_t kwb = (kk * 8) * 4;   // k offset in bytes (words*4)
            uint32_t ah[4][4], al[4][4];
#pragma unroll
            for (int mt = 0; mt < 4; mt++) {
                uint32_t ro = (uint32_t)((warp_m + mt * 16 + a_row) * RSTR + a_kw) * 4 + kwb;
                LDSMX4(ah[mt][0], ah[mt][1], ah[mt][2], ah[mt][3], AHo + ro);
                LDSMX4(al[mt][0], al[mt][1], al[mt][2], al[mt][3], ALo + ro);
            }
#pragma unroll
            for (int c = 0; c < 2; ++c) {
                uint32_t bh[4], bl[4];
                uint32_t ro = (uint32_t)((warp_n + c * 16 + b_row) * RSTR + b_kw) * 4 + kwb;
                LDSMX4(bh[0], bh[1], bh[2], bh[3], BHo + ro);
                LDSMX4(bl[0], bl[1], bl[2], bl[3], BLo + ro);
                // pass 1: hi*hi
#pragma unroll
                for (int mt = 0; mt < 4; mt++) {
                    mma16816(acc[mt][2 * c],     ah[mt][0], ah[mt][1], ah[mt][2], ah[mt][3], bh[0], bh[1]);
                    mma16816(acc[mt][2 * c + 1], ah[mt][0], ah[mt][1], ah[mt][2], ah[mt][3], bh[2], bh[3]);
                }
                // pass 2: lo*hi (B regs reused)
#pragma unroll
                for (int mt = 0; mt < 4; mt++) {
                    mma16816(acc[mt][2 * c],     al[mt][0], al[mt][1], al[mt][2], al[mt][3], bh[0], bh[1]);
                    mma16816(acc[mt][2 * c + 1], al[mt][0], al[mt][1], al[mt][2], al[mt][3], bh[2], bh[3]);
                }
                // pass 3: hi*lo (A regs reused)
#pragma unroll
                for (int mt = 0; mt < 4; mt++) {
                    mma16816(acc[mt][2 * c],     ah[mt][0], ah[mt][1], ah[mt][2], ah[mt][3], bl[0], bl[1]);
                    mma16816(acc[mt][2 * c + 1], ah[mt][0], ah[mt][1], ah[mt][2], ah[mt][3], bl[2], bl[3]);
                }
            }
        }
        __syncthreads();
        if (it + 2 < NIT) load_stage(it + 2, it & 1);
        CP_COMMIT();
    }

    const int g = lane >> 2, tig = lane & 3;
#pragma unroll
    for (int mt = 0; mt < 4; mt++) {
#pragma unroll
        for (int nt = 0; nt < 4; nt++) {
            int row = by + warp_m + mt * 16 + g;
            int col = bx + warp_n + nt * 8 + 2 * tig;
            *(float2*)&C[(size_t)row * N + col]       = make_float2(acc[mt][nt][0], acc[mt][nt][1]);
            *(float2*)&C[(size_t)(row + 8) * N + col] = make_float2(acc[mt][nt][2], acc[mt][nt][3]);
        }
    }
}

// ---------------- operand prep ----------------
// hidden_states -> fp16 hi/lo planes (row-major [s][k])
__global__ void split_a_kernel(const float* __restrict__ src)
{
    int i = blockIdx.x * 256 + threadIdx.x;
    float x = src[i];
    __half h = __float2half_rn(x);
    g_ha_hi[i] = h;
    g_ha_lo[i] = __float2half_rn(x - __half2float(h));
}

// transpose + split: W [K][Nw] fp32 row-major -> out planes [n][k] fp16, rows offset nbase
__global__ void tsplit_kernel(const float* __restrict__ W, __half* __restrict__ outH,
                              __half* __restrict__ outL, int Nw, int nbase)
{
    __shared__ float tile[32][33];
    int n0 = blockIdx.x * 32;
    int k0 = blockIdx.y * 32;
    int tx = threadIdx.x, ty = threadIdx.y;
#pragma unroll
    for (int i = 0; i < 4; i++)
        tile[ty + i * 8][tx] = W[(size_t)(k0 + ty + i * 8) * Nw + n0 + tx];
    __syncthreads();
#pragma unroll
    for (int i = 0; i < 4; i++) {
        int n = n0 + ty + i * 8;
        int k = k0 + tx;
        float x = tile[tx][ty + i * 8];
        __half h = __float2half_rn(x);
        outH[(size_t)(nbase + n) * HID + k] = h;
        outL[(size_t)(nbase + n) * HID + k] = __float2half_rn(x - __half2float(h));
    }
}

// ---------------- RoPE tables ----------------
__global__ void invf_kernel()
{
    int j = threadIdx.x;
    g_invf[j] = pow(10000.0, -(double)(2 * j) / 128.0);
}

__global__ void rope_table_kernel(const int* __restrict__ pos)
{
    int s = blockIdx.x;
    int j = threadIdx.x;
    double ang = (double)pos[s] * g_invf[j];
    double r = fmod(ang, 6.283185307179586476925286766559);
    float sv, cv;
    sincosf((float)r, &sv, &cv);
    g_cos[s * 64 + j] = cv;
    g_sin[s * 64 + j] = sv;
}

__global__ void rope_kernel(float* __restrict__ buf, int stride)
{
    int s = blockIdx.x;
    int h = blockIdx.y;
    int d = threadIdx.x;
    __shared__ float row[DH];
    float x = buf[(size_t)s * stride + h * DH + d];
    row[d] = x;
    __syncthreads();
    float part = (d < 64) ? -row[d + 64] : row[d - 64];
    float c  = g_cos[s * 64 + (d & 63)];
    float sn = g_sin[s * 64 + (d & 63)];
    buf[(size_t)s * stride + h * DH + d] = x * c + part * sn;
}

// ---------------- sketch ----------------
__global__ void sketch_kernel(const float* __restrict__ buf, const float* __restrict__ Hm,
                              float* __restrict__ Sout, int stride)
{
    int n = blockIdx.x;
    int h = blockIdx.y;
    int d = threadIdx.x;
    __shared__ float mv[DH];
    float sum = 0.0f;
#pragma unroll 8
    for (int r = 0; r < BLKQ; r++)
        sum += buf[(size_t)(n * BLKQ + r) * stride + h * DH + d];
    mv[d] = sum * (1.0f / 64.0f);
    __syncthreads();
    if (d < MSK) {
        float acc = 0.0f;
#pragma unroll 8
        for (int dd = 0; dd < DH; dd++)
            acc += mv[dd] * Hm[dd * MSK + d];
        Sout[(h * NBLK + n) * MSK + d] = acc;
    }
}

// ---------------- block-score + top-k ----------------
__global__ void topk_kernel()
{
    int i = blockIdx.x;
    int h = blockIdx.y;
    int j = threadIdx.x;
    __shared__ float bs[NBLK];

    float val;
    if (j > i) {
        val = NEGV;
    } else {
        const float* sq = &g_Sq[(h * NBLK + i) * MSK];
        const float* sk = &g_Sk[((h >> 2) * NBLK + j) * MSK];
        float acc = 0.0f;
#pragma unroll
        for (int m = 0; m < MSK; m++) acc += sq[m] * sk[m];
        val = acc;
    }
    if (j == i) val = 1000000000.0f;
    bs[j] = val;
    __syncthreads();

    if (j == 0) {
        for (int t = 0; t < KTOP; t++) {
            float best = -INFINITY;
            int bi = 0;
            for (int c = 0; c < NBLK; c++) {
                if (bs[c] > best) { best = bs[c]; bi = c; }
            }
            g_topk[(h * NBLK + i) * KTOP + t] = bi;
            bs[bi] = -INFINITY;
        }
    }
}

// =======================================================================
// sparse flash attention via m16n8k16 HMMA (unchanged from R12, verified)
// =======================================================================
#define AQ_STR 68
#define KS_STR 73
#define VS_STR 136
#define Q_PLANE (64 * AQ_STR)
#define K_PLANE (64 * KS_STR)
#define V_PLANE (32 * VS_STR)
#define ATT_SMEM_W (2 * Q_PLANE + 2 * K_PLANE)
#define ATT_SMEM_BYTES (ATT_SMEM_W * 4)

__global__ __launch_bounds__(128) void attn_kernel()
{
    extern __shared__ uint32_t smw[];
    uint32_t* Qh = smw;
    uint32_t* Ql = smw + Q_PLANE;
    uint32_t* Kh = smw + 2 * Q_PLANE;
    uint32_t* Kl = Kh + K_PLANE;
    uint32_t* Vh = Kh;
    uint32_t* Vl = Kh + V_PLANE;

    const int i   = blockIdx.x;
    const int h   = blockIdx.y;
    const int kvh = h >> 2;
    const int t    = threadIdx.x;
    const int warp = t >> 5;
    const int lane = t & 31;
    const int g    = lane >> 2;
    const int tig  = lane & 3;
    const int wm   = warp * 16;

    const float QSCALE = 0.12753100795667498f;  // 1/sqrt(128) * log2(e)

    for (int idx = t; idx < 64 * 64; idx += 128) {
        int r  = idx >> 6;
        int k2 = idx & 63;
        float2 q = *(const float2*)&g_qkv[(size_t)(i * BLKQ + r) * QKVN + h * DH + 2 * k2];
        uint32_t H, L;
        split2(q.x * QSCALE, q.y * QSCALE, H, L);
        Qh[r * AQ_STR + k2] = H;
        Ql[r * AQ_STR + k2] = L;
    }

    float O[16][4];
#pragma unroll
    for (int nt = 0; nt < 16; nt++)
#pragma unroll
        for (int r = 0; r < 4; r++) O[nt][r] = 0.0f;

    float m0 = -INFINITY, m1 = -INFINITY, l0 = 0.0f, l1 = 0.0f;
    const int qp0 = i * BLKQ + wm + g;
    const int qp1 = qp0 + 8;

    for (int kb = 0; kb < KTOP; kb++) {
        const int j = g_topk[(h * NBLK + i) * KTOP + kb];

        __syncthreads();
        for (int idx = t; idx < 64 * 64; idx += 128) {
            int c  = idx >> 6;
            int d2 = idx & 63;
            float2 kv = *(const float2*)&g_qkv[(size_t)(j * BLKQ + c) * QKVN + 2048 + kvh * DH + 2 * d2];
            uint32_t H, L;
            split2(kv.x, kv.y, H, L);
            Kh[d2 * KS_STR + c] = H;
            Kl[d2 * KS_STR + c] = L;
        }
        __syncthreads();

        float acc[8][4];
#pragma unroll
        for (int nt = 0; nt < 8; nt++)
#pragma unroll
            for (int r = 0; r < 4; r++) acc[nt][r] = 0.0f;

#pragma unroll
        for (int ks = 0; ks < 8; ++ks) {
            int a0i = (wm + g) * AQ_STR + ks * 8 + tig;
            uint32_t ah0 = Qh[a0i], ah1 = Qh[a0i + 8 * AQ_STR];
            uint32_t ah2 = Qh[a0i + 4], ah3 = Qh[a0i + 8 * AQ_STR + 4];
            uint32_t al0 = Ql[a0i], al1 = Ql[a0i + 8 * AQ_STR];
            uint32_t al2 = Ql[a0i + 4], al3 = Ql[a0i + 8 * AQ_STR + 4];
#pragma unroll
            for (int nt = 0; nt < 8; ++nt) {
                int b0i = (ks * 8 + tig) * KS_STR + nt * 8 + g;
                int b1i = b0i + 4 * KS_STR;
                uint32_t bh0 = Kh[b0i], bh1 = Kh[b1i];
                uint32_t bl0 = Kl[b0i], bl1 = Kl[b1i];
                mma16816(acc[nt], ah0, ah1, ah2, ah3, bh0, bh1);
                mma16816(acc[nt], ah0, ah1, ah2, ah3, bl0, bl1);
                mma16816(acc[nt], al0, al1, al2, al3, bh0, bh1);
            }
        }

        const int kbase = j * BLKQ;
#pragma unroll
        for (int nt = 0; nt < 8; ++nt) {
            int c0 = kbase + nt * 8 + 2 * tig;
            if (c0 > qp0)     acc[nt][0] = -INFINITY;
            if (c0 + 1 > qp0) acc[nt][1] = -INFINITY;
            if (c0 > qp1)     acc[nt][2] = -INFINITY;
            if (c0 + 1 > qp1) acc[nt][3] = -INFINITY;
        }
        float rm0 = -INFINITY, rm1 = -INFINITY;
#pragma unroll
        for (int nt = 0; nt < 8; ++nt) {
            rm0 = fmaxf(rm0, fmaxf(acc[nt][0], acc[nt][1]));
            rm1 = fmaxf(rm1, fmaxf(acc[nt][2], acc[nt][3]));
        }
        rm0 = fmaxf(rm0, __shfl_xor_sync(0xffffffffu, rm0, 1));
        rm0 = fmaxf(rm0, __shfl_xor_sync(0xffffffffu, rm0, 2));
        rm1 = fmaxf(rm1, __shfl_xor_sync(0xffffffffu, rm1, 1));
        rm1 = fmaxf(rm1, __shfl_xor_sync(0xffffffffu, rm1, 2));

        float mn0 = fmaxf(m0, rm0), mn1 = fmaxf(m1, rm1);
        float al0f = exp2f(m0 - mn0), al1f = exp2f(m1 - mn1);
        m0 = mn0; m1 = mn1;

        float s0 = 0.0f, s1 = 0.0f;
#pragma unroll
        for (int nt = 0; nt < 8; ++nt) {
            acc[nt][0] = exp2f(acc[nt][0] - mn0);
            acc[nt][1] = exp2f(acc[nt][1] - mn0);
            acc[nt][2] = exp2f(acc[nt][2] - mn1);
            acc[nt][3] = exp2f(acc[nt][3] - mn1);
            s0 += acc[nt][0] + acc[nt][1];
            s1 += acc[nt][2] + acc[nt][3];
        }
        s0 += __shfl_xor_sync(0xffffffffu, s0, 1);
        s0 += __shfl_xor_sync(0xffffffffu, s0, 2);
        s1 += __shfl_xor_sync(0xffffffffu, s1, 1);
        s1 += __shfl_xor_sync(0xffffffffu, s1, 2);
        l0 = l0 * al0f + s0;
        l1 = l1 * al1f + s1;

#pragma unroll
        for (int nt = 0; nt < 16; ++nt) {
            O[nt][0] *= al0f; O[nt][1] *= al0f;
            O[nt][2] *= al1f; O[nt][3] *= al1f;
        }

        __syncthreads();
        for (int idx = t; idx < 32 * 128; idx += 128) {
            int c2 = idx >> 7;
            int dd = idx & 127;
            size_t base = (size_t)(j * BLKQ + 2 * c2) * QKVN + 2560 + kvh * DH + dd;
            float v0 = g_qkv[base];
            float v1 = g_qkv[base + QKVN];
            uint32_t H, L;
            split2(v0, v1, H, L);
            Vh[c2 * VS_STR + dd] = H;
            Vl[c2 * VS_STR + dd] = L;
        }
        __syncthreads();

#pragma unroll
        for (int kk = 0; kk < 4; ++kk) {
            uint32_t ah0, ah1, ah2, ah3, al0_, al1_, al2_, al3_;
            split2(acc[2 * kk][0],     acc[2 * kk][1],     ah0, al0_);
            split2(acc[2 * kk][2],     acc[2 * kk][3],     ah1, al1_);
            split2(acc[2 * kk + 1][0], acc[2 * kk + 1][1], ah2, al2_);
            split2(acc[2 * kk + 1][2], acc[2 * kk + 1][3], ah3, al3_);
#pragma unroll
            for (int nt = 0; nt < 16; ++nt) {
                int b0i = (kk * 8 + tig) * VS_STR + nt * 8 + g;
                int b1i = b0i + 4 * VS_STR;
                uint32_t bh0 = Vh[b0i], bh1 = Vh[b1i];
                uint32_t bl0 = Vl[b0i], bl1 = Vl[b1i];
                mma16816(O[nt], ah0, ah1, ah2, ah3, bh0, bh1);
                mma16816(O[nt], al0_, al1_, al2_, al3_, bh0, bh1);
                mma16816(O[nt], ah0, ah1, ah2, ah3, bl0, bl1);
            }
        }
    }

    float inv0 = 1.0f / l0, inv1 = 1.0f / l1;
    int row0 = i * BLKQ + wm + g;
    int row1 = row0 + 8;
#pragma unroll
    for (int nt = 0; nt < 16; ++nt) {
        int d0 = nt * 8 + 2 * tig;
        uint32_t H, L;
        split2(O[nt][0] * inv0, O[nt][1] * inv0, H, L);
        *(uint32_t*)&g_oa_hi[(size_t)row0 * HID + h * DH + d0] = H;
        *(uint32_t*)&g_oa_lo[(size_t)row0 * HID + h * DH + d0] = L;
        split2(O[nt][2] * inv1, O[nt][3] * inv1, H, L);
        *(uint32_t*)&g_oa_hi[(size_t)row1 * HID + h * DH + d0] = H;
        *(uint32_t*)&g_oa_lo[(size_t)row1 * HID + h * DH + d0] = L;
    }
}

// ---------------- launch ----------------
extern "C" void kernel_launch(void* const* d_in, const int* in_sizes, int n_in,
                              void* d_out, int out_size)
{
    const float* hs  = (const float*)d_in[0];
    const int*   pos = (const int*)d_in[1];
    const float* Wq  = (const float*)d_in[2];
    const float* Wk  = (const float*)d_in[3];
    const float* Wv  = (const float*)d_in[4];
    const float* Wo  = (const float*)d_in[5];
    const float* Hm  = (const float*)d_in[6];
    float* out = (float*)d_out;

    float *qkv, *Sq, *Sk;
    __half *ha_hi, *ha_lo, *oa_hi, *oa_lo, *wb_hi, *wb_lo, *wob_hi, *wob_lo;
    cudaGetSymbolAddress((void**)&qkv,    g_qkv);
    cudaGetSymbolAddress((void**)&Sq,     g_Sq);
    cudaGetSymbolAddress((void**)&Sk,     g_Sk);
    cudaGetSymbolAddress((void**)&ha_hi,  g_ha_hi);
    cudaGetSymbolAddress((void**)&ha_lo,  g_ha_lo);
    cudaGetSymbolAddress((void**)&oa_hi,  g_oa_hi);
    cudaGetSymbolAddress((void**)&oa_lo,  g_oa_lo);
    cudaGetSymbolAddress((void**)&wb_hi,  g_wb_hi);
    cudaGetSymbolAddress((void**)&wb_lo,  g_wb_lo);
    cudaGetSymbolAddress((void**)&wob_hi, g_wob_hi);
    cudaGetSymbolAddress((void**)&wob_lo, g_wob_lo);

    cudaFuncSetAttribute(gemm_fp16_kernel, cudaFuncAttributeMaxDynamicSharedMemorySize,
                         GEMM_SMEM_BYTES);
    cudaFuncSetAttribute(attn_kernel, cudaFuncAttributeMaxDynamicSharedMemorySize,
                         ATT_SMEM_BYTES);

    // operand prep: A planes + transposed/split weight planes [n][k]
    split_a_kernel<<<SEQ * HID / 256, 256>>>(hs);
    tsplit_kernel<<<dim3(2048 / 32, HID / 32), dim3(32, 8)>>>(Wq, wb_hi, wb_lo, 2048, 0);
    tsplit_kernel<<<dim3(512 / 32,  HID / 32), dim3(32, 8)>>>(Wk, wb_hi, wb_lo, 512, 2048);
    tsplit_kernel<<<dim3(512 / 32,  HID / 32), dim3(32, 8)>>>(Wv, wb_hi, wb_lo, 512, 2560);
    tsplit_kernel<<<dim3(2048 / 32, HID / 32), dim3(32, 8)>>>(Wo, wob_hi, wob_lo, 2048, 0);

    // fused QKV projection
    gemm_fp16_kernel<<<dim3(QKVN / 128, SEQ / 128), 256, GEMM_SMEM_BYTES>>>(
        ha_hi, ha_lo, wb_hi, wb_lo, qkv, SEQ, QKVN, HID);

    // RoPE
    invf_kernel<<<1, 64>>>();
    rope_table_kernel<<<SEQ, 64>>>(pos);
    rope_kernel<<<dim3(SEQ, NH), DH>>>(qkv, QKVN);
    rope_kernel<<<dim3(SEQ, NKV), DH>>>(qkv + 2048, QKVN);

    // sketches
    sketch_kernel<<<dim3(NBLK, NH), DH>>>(qkv, Hm, Sq, QKVN);
    sketch_kernel<<<dim3(NBLK, NKV), DH>>>(qkv + 2048, Hm, Sk, QKVN);

    // block scores + top-k
    topk_kernel<<<dim3(NBLK, NH), 64>>>();

    // sparse attention (tensor-core, emits fp16 split planes)
    attn_kernel<<<dim3(NBLK, NH), 128, ATT_SMEM_BYTES>>>();

    // output projection
    gemm_fp16_kernel<<<dim3(HID / 128, SEQ / 128), 256, GEMM_SMEM_BYTES>>>(
        oa_hi, oa_lo, wob_hi, wob_lo, out, SEQ, HID, HID);
}

// round 14
// speedup vs baseline: 1.3595x; 1.3595x over previous
#include <cuda_runtime.h>
#include <cuda_fp16.h>
#include <math.h>
#include <stdint.h>

// ---------------- problem constants ----------------
#define SEQ   4096
#define HID   2048
#define NH    16
#define NKV   4
#define DH    128
#define BLKQ  64
#define NBLK  64
#define MSK   32
#define KTOP  8
#define QKVN  3072          // fused QKV output columns (2048 q | 512 k | 512 v)

#define NEGV  (-1000000000.0f)

// ---------------- scratch (device globals; no allocation allowed) ----------------
__device__ float  g_qkv[SEQ * QKVN];         // fused q|k|v fp32, layout [s][3072]
__device__ __half g_ha_hi[SEQ * HID];        // hidden_states hi plane [s][k]
__device__ __half g_ha_lo[SEQ * HID];        // hidden_states lo plane
__device__ __half2 g_wb_hi[(HID/2) * QKVN];  // packed W_qkv hi, k-pair interleaved [k2][n]
__device__ __half2 g_wb_lo[(HID/2) * QKVN];
__device__ __half g_oa_hi[SEQ * HID];        // attention-out hi plane [s][n]
__device__ __half g_oa_lo[SEQ * HID];
__device__ __half2 g_wob_hi[(HID/2) * HID];  // Wo hi, k-pair interleaved [k2][n]
__device__ __half2 g_wob_lo[(HID/2) * HID];
__device__ float  g_Sq[NH * NBLK * MSK];
__device__ float  g_Sk[NKV * NBLK * MSK];
__device__ int    g_topk[NH * NBLK * KTOP];
__device__ float  g_cos[SEQ * 64];
__device__ float  g_sin[SEQ * 64];
__device__ double g_invf[64];

// ---------------- common fp16 helpers ----------------
__device__ __forceinline__ uint32_t smem_u32(const void* p) {
    uint32_t a;
    asm("{ .reg .u64 t; cvta.to.shared.u64 t, %1; cvt.u32.u64 %0, t; }" : "=r"(a) : "l"(p));
    return a;
}
__device__ __forceinline__ void mma16816(float c[4],
    uint32_t a0, uint32_t a1, uint32_t a2, uint32_t a3, uint32_t b0, uint32_t b1)
{
    asm volatile(
        "mma.sync.aligned.m16n8k16.row.col.f32.f16.f16.f32 "
        "{%0,%1,%2,%3}, {%4,%5,%6,%7}, {%8,%9}, {%0,%1,%2,%3};"
        : "+f"(c[0]), "+f"(c[1]), "+f"(c[2]), "+f"(c[3])
        : "r"(a0), "r"(a1), "r"(a2), "r"(a3), "r"(b0), "r"(b1));
}
__device__ __forceinline__ void split2(float x, float y, uint32_t& H, uint32_t& L) {
    __half hx = __float2half_rn(x), hy = __float2half_rn(y);
    __half2 hh = __halves2half2(hx, hy);
    H = *(uint32_t*)&hh;
    __half2 ll = __halves2half2(__float2half_rn(x - __half2float(hx)),
                                __float2half_rn(y - __half2float(hy)));
    L = *(uint32_t*)&ll;
}

// =======================================================================
// fp16 split GEMM (R12-verified): C[M,N] = A[M,K] @ B[K,N]
// A planes row-major fp16 [M][K]; B planes half2 k-pair interleaved [K/2][N].
// CTA 128x128, BK=32, 256 threads, warp tile 64x32, cp.async double-buffered.
// PASSES=3: hh + h*l + l*h (~fp32).  PASSES=2: hh + h*l (A-lo never touched).
// =======================================================================
#define A_STR2 20
#define B_STR2 136
#define A_PLANE_W (128 * A_STR2)
#define B_PLANE_W (16 * B_STR2)
#define STAGE_W   (2 * A_PLANE_W + 2 * B_PLANE_W)
#define GEMM_SMEM_BYTES (2 * STAGE_W * 4)

#define CP16(dst, src) \
    asm volatile("cp.async.cg.shared.global [%0], [%1], 16;" :: "r"(dst), "l"(src))
#define CP_COMMIT() asm volatile("cp.async.commit_group;")
#define CP_WAIT1()  asm volatile("cp.async.wait_group 1;")

template <int PASSES>
__global__ __launch_bounds__(256, 2) void gemm_fp16_kernel(
    const __half* __restrict__ Ah, const __half* __restrict__ Al,
    const __half2* __restrict__ Bh, const __half2* __restrict__ Bl,
    float* __restrict__ C, int M, int N, int K)
{
    extern __shared__ uint32_t smw[];
    const uint32_t smb = smem_u32(smw);

    const int bx = blockIdx.x * 128;
    const int by = blockIdx.y * 128;
    const int tid  = threadIdx.x;
    const int warp = tid >> 5;
    const int lane = tid & 31;
    const int g    = lane >> 2;
    const int tig  = lane & 3;
    const int warp_m = (warp & 1) * 64;
    const int warp_n = (warp >> 1) * 32;

    const int NIT = K / 32;
    const int ar = tid >> 2;
    const int ac = (tid & 3) * 16;
    const int bk = tid >> 5;
    const int bn = (tid & 31) * 16;

    auto load_stage = [&](int it, int s) {
        const int kt = it * 32;
        const uint32_t base = smb + (uint32_t)s * (STAGE_W * 4);
        {
            const char* sh = (const char*)(Ah + (size_t)(by + ar) * K + kt);
            CP16(base + ar * 80 + ac, sh + ac);
            const char* sh2 = (const char*)(Ah + (size_t)(by + ar + 64) * K + kt);
            CP16(base + (ar + 64) * 80 + ac, sh2 + ac);
            if (PASSES == 3) {
                const char* sl = (const char*)(Al + (size_t)(by + ar) * K + kt);
                CP16(base + A_PLANE_W * 4 + ar * 80 + ac, sl + ac);
                const char* sl2 = (const char*)(Al + (size_t)(by + ar + 64) * K + kt);
                CP16(base + A_PLANE_W * 4 + (ar + 64) * 80 + ac, sl2 + ac);
            }
        }
        {
            const uint32_t bb = base + 2 * A_PLANE_W * 4;
            const char* sh = (const char*)(Bh + (size_t)(kt / 2 + bk) * N + bx);
            const char* sl = (const char*)(Bl + (size_t)(kt / 2 + bk) * N + bx);
            CP16(bb + bk * 544 + bn, sh + bn);
            CP16(bb + B_PLANE_W * 4 + bk * 544 + bn, sl + bn);
            const char* sh2 = (const char*)(Bh + (size_t)(kt / 2 + bk + 8) * N + bx);
            const char* sl2 = (const char*)(Bl + (size_t)(kt / 2 + bk + 8) * N + bx);
            CP16(bb + (bk + 8) * 544 + bn, sh2 + bn);
            CP16(bb + B_PLANE_W * 4 + (bk + 8) * 544 + bn, sl2 + bn);
        }
    };

    float acc[4][4][4];
#pragma unroll
    for (int mt = 0; mt < 4; mt++)
#pragma unroll
        for (int nt = 0; nt < 4; nt++)
#pragma unroll
            for (int r = 0; r < 4; r++) acc[mt][nt][r] = 0.0f;

    load_stage(0, 0); CP_COMMIT();
    load_stage(1, 1); CP_COMMIT();

    for (int it = 0; it < NIT; ++it) {
        CP_WAIT1();
        __syncthreads();

        const uint32_t* st = smw + (it & 1) * STAGE_W;
        const uint32_t* AH = st;
        const uint32_t* AL = st + A_PLANE_W;
        const uint32_t* BH = st + 2 * A_PLANE_W;
        const uint32_t* BL = BH + B_PLANE_W;

#pragma unroll
        for (int kk = 0; kk < 2; ++kk) {
            uint32_t a[4][4], bh[4][2], bl[4][2];
#pragma unroll
            for (int nt = 0; nt < 4; nt++) {
                int n = warp_n + nt * 8 + g;
                bh[nt][0] = BH[(kk * 8 + tig) * B_STR2 + n];
                bh[nt][1] = BH[(kk * 8 + tig + 4) * B_STR2 + n];
                bl[nt][0] = BL[(kk * 8 + tig) * B_STR2 + n];
                bl[nt][1] = BL[(kk * 8 + tig + 4) * B_STR2 + n];
            }
#pragma unroll
            for (int mt = 0; mt < 4; mt++) {
                int row = warp_m + mt * 16 + g;
                a[mt][0] = AH[row * A_STR2 + kk * 8 + tig];
                a[mt][1] = AH[(row + 8) * A_STR2 + kk * 8 + tig];
                a[mt][2] = AH[row * A_STR2 + kk * 8 + tig + 4];
                a[mt][3] = AH[(row + 8) * A_STR2 + kk * 8 + tig + 4];
            }
            // pass 1: hi * hi
#pragma unroll
            for (int mt = 0; mt < 4; mt++)
#pragma unroll
                for (int nt = 0; nt < 4; nt++)
                    mma16816(acc[mt][nt], a[mt][0], a[mt][1], a[mt][2], a[mt][3],
                             bh[nt][0], bh[nt][1]);
            // pass 2: hi * lo
#pragma unroll
            for (int mt = 0; mt < 4; mt++)
#pragma unroll
                for (int nt = 0; nt < 4; nt++)
                    mma16816(acc[mt][nt], a[mt][0], a[mt][1], a[mt][2], a[mt][3],
                             bl[nt][0], bl[nt][1]);
            if (PASSES == 3) {
                // pass 3: lo * hi (reload A as lo plane)
#pragma unroll
                for (int mt = 0; mt < 4; mt++) {
                    int row = warp_m + mt * 16 + g;
                    a[mt][0] = AL[row * A_STR2 + kk * 8 + tig];
                    a[mt][1] = AL[(row + 8) * A_STR2 + kk * 8 + tig];
                    a[mt][2] = AL[row * A_STR2 + kk * 8 + tig + 4];
                    a[mt][3] = AL[(row + 8) * A_STR2 + kk * 8 + tig + 4];
                }
#pragma unroll
                for (int mt = 0; mt < 4; mt++)
#pragma unroll
                    for (int nt = 0; nt < 4; nt++)
                        mma16816(acc[mt][nt], a[mt][0], a[mt][1], a[mt][2], a[mt][3],
                                 bh[nt][0], bh[nt][1]);
            }
        }
        __syncthreads();
        if (it + 2 < NIT) load_stage(it + 2, it & 1);
        CP_COMMIT();
    }

#pragma unroll
    for (int mt = 0; mt < 4; mt++) {
#pragma unroll
        for (int nt = 0; nt < 4; nt++) {
            int row = by + warp_m + mt * 16 + g;
            int col = bx + warp_n + nt * 8 + 2 * tig;
            *(float2*)&C[(size_t)row * N + col]       = make_float2(acc[mt][nt][0], acc[mt][nt][1]);
            *(float2*)&C[(size_t)(row + 8) * N + col] = make_float2(acc[mt][nt][2], acc[mt][nt][3]);
        }
    }
}

// ---------------- operand prep kernels ----------------
__global__ void split_a_kernel(const float* __restrict__ src)
{
    int i = blockIdx.x * 256 + threadIdx.x;
    float x = src[i];
    __half h = __float2half_rn(x);
    g_ha_hi[i] = h;
    g_ha_lo[i] = __float2half_rn(x - __half2float(h));
}

__global__ void pack_split_w_kernel(const float* __restrict__ Wq,
                                    const float* __restrict__ Wk,
                                    const float* __restrict__ Wv)
{
    int k2 = blockIdx.y;
    int j  = blockIdx.x * 256 + threadIdx.x;
    const float* W; int col, width;
    if (j < 2048)      { W = Wq; col = j;        width = 2048; }
    else if (j < 2560) { W = Wk; col = j - 2048; width = 512;  }
    else               { W = Wv; col = j - 2560; width = 512;  }
    float x0 = W[(size_t)(2 * k2) * width + col];
    float x1 = W[(size_t)(2 * k2 + 1) * width + col];
    uint32_t H, L;
    split2(x0, x1, H, L);
    g_wb_hi[(size_t)k2 * QKVN + j] = *(__half2*)&H;
    g_wb_lo[(size_t)k2 * QKVN + j] = *(__half2*)&L;
}

__global__ void split_wo_kernel(const float* __restrict__ Wo)
{
    int k2 = blockIdx.y;
    int n  = blockIdx.x * 256 + threadIdx.x;
    float x0 = Wo[(size_t)(2 * k2) * HID + n];
    float x1 = Wo[(size_t)(2 * k2 + 1) * HID + n];
    uint32_t H, L;
    split2(x0, x1, H, L);
    g_wob_hi[(size_t)k2 * HID + n] = *(__half2*)&H;
    g_wob_lo[(size_t)k2 * HID + n] = *(__half2*)&L;
}

// ---------------- RoPE tables ----------------
__global__ void invf_kernel()
{
    int j = threadIdx.x;
    g_invf[j] = pow(10000.0, -(double)(2 * j) / 128.0);
}

__global__ void rope_table_kernel(const int* __restrict__ pos)
{
    int s = blockIdx.x;
    int j = threadIdx.x;
    double ang = (double)pos[s] * g_invf[j];
    double r = fmod(ang, 6.283185307179586476925286766559);
    float sv, cv;
    sincosf((float)r, &sv, &cv);
    g_cos[s * 64 + j] = cv;
    g_sin[s * 64 + j] = sv;
}

__global__ void rope_kernel(float* __restrict__ buf, int stride)
{
    int s = blockIdx.x;
    int h = blockIdx.y;
    int d = threadIdx.x;
    __shared__ float row[DH];
    float x = buf[(size_t)s * stride + h * DH + d];
    row[d] = x;
    __syncthreads();
    float part = (d < 64) ? -row[d + 64] : row[d - 64];
    float c  = g_cos[s * 64 + (d & 63)];
    float sn = g_sin[s * 64 + (d & 63)];
    buf[(size_t)s * stride + h * DH + d] = x * c + part * sn;
}

// ---------------- sketch ----------------
__global__ void sketch_kernel(const float* __restrict__ buf, const float* __restrict__ Hm,
                              float* __restrict__ Sout, int stride)
{
    int n = blockIdx.x;
    int h = blockIdx.y;
    int d = threadIdx.x;
    __shared__ float mv[DH];
    float sum = 0.0f;
#pragma unroll 8
    for (int r = 0; r < BLKQ; r++)
        sum += buf[(size_t)(n * BLKQ + r) * stride + h * DH + d];
    mv[d] = sum * (1.0f / 64.0f);
    __syncthreads();
    if (d < MSK) {
        float acc = 0.0f;
#pragma unroll 8
        for (int dd = 0; dd < DH; dd++)
            acc += mv[dd] * Hm[dd * MSK + d];
        Sout[(h * NBLK + n) * MSK + d] = acc;
    }
}

// ---------------- block-score + top-k ----------------
__global__ void topk_kernel()
{
    int i = blockIdx.x;
    int h = blockIdx.y;
    int j = threadIdx.x;
    __shared__ float bs[NBLK];

    float val;
    if (j > i) {
        val = NEGV;
    } else {
        const float* sq = &g_Sq[(h * NBLK + i) * MSK];
        const float* sk = &g_Sk[((h >> 2) * NBLK + j) * MSK];
        float acc = 0.0f;
#pragma unroll
        for (int m = 0; m < MSK; m++) acc += sq[m] * sk[m];
        val = acc;
    }
    if (j == i) val = 1000000000.0f;
    bs[j] = val;
    __syncthreads();

    if (j == 0) {
        for (int t = 0; t < KTOP; t++) {
            float best = -INFINITY;
            int bi = 0;
            for (int c = 0; c < NBLK; c++) {
                if (bs[c] > best) { best = bs[c]; bi = c; }
            }
            g_topk[(h * NBLK + i) * KTOP + t] = bi;
            bs[bi] = -INFINITY;
        }
    }
}

// =======================================================================
// sparse flash attention via m16n8k16 HMMA (unchanged, verified)
// =======================================================================
#define AQ_STR 68
#define KS_STR 73
#define VS_STR 136
#define Q_PLANE (64 * AQ_STR)
#define K_PLANE (64 * KS_STR)
#define V_PLANE (32 * VS_STR)
#define ATT_SMEM_W (2 * Q_PLANE + 2 * K_PLANE)
#define ATT_SMEM_BYTES (ATT_SMEM_W * 4)

__global__ __launch_bounds__(128) void attn_kernel()
{
    extern __shared__ uint32_t smw[];
    uint32_t* Qh = smw;
    uint32_t* Ql = smw + Q_PLANE;
    uint32_t* Kh = smw + 2 * Q_PLANE;
    uint32_t* Kl = Kh + K_PLANE;
    uint32_t* Vh = Kh;
    uint32_t* Vl = Kh + V_PLANE;

    const int i   = blockIdx.x;
    const int h   = blockIdx.y;
    const int kvh = h >> 2;
    const int t    = threadIdx.x;
    const int warp = t >> 5;
    const int lane = t & 31;
    const int g    = lane >> 2;
    const int tig  = lane & 3;
    const int wm   = warp * 16;

    const float QSCALE = 0.12753100795667498f;  // 1/sqrt(128) * log2(e)

    for (int idx = t; idx < 64 * 64; idx += 128) {
        int r  = idx >> 6;
        int k2 = idx & 63;
        float2 q = *(const float2*)&g_qkv[(size_t)(i * BLKQ + r) * QKVN + h * DH + 2 * k2];
        uint32_t H, L;
        split2(q.x * QSCALE, q.y * QSCALE, H, L);
        Qh[r * AQ_STR + k2] = H;
        Ql[r * AQ_STR + k2] = L;
    }

    float O[16][4];
#pragma unroll
    for (int nt = 0; nt < 16; nt++)
#pragma unroll
        for (int r = 0; r < 4; r++) O[nt][r] = 0.0f;

    float m0 = -INFINITY, m1 = -INFINITY, l0 = 0.0f, l1 = 0.0f;
    const int qp0 = i * BLKQ + wm + g;
    const int qp1 = qp0 + 8;

    for (int kb = 0; kb < KTOP; kb++) {
        const int j = g_topk[(h * NBLK + i) * KTOP + kb];

        __syncthreads();
        for (int idx = t; idx < 64 * 64; idx += 128) {
            int c  = idx >> 6;
            int d2 = idx & 63;
            float2 kv = *(const float2*)&g_qkv[(size_t)(j * BLKQ + c) * QKVN + 2048 + kvh * DH + 2 * d2];
            uint32_t H, L;
            split2(kv.x, kv.y, H, L);
            Kh[d2 * KS_STR + c] = H;
            Kl[d2 * KS_STR + c] = L;
        }
        __syncthreads();

        float acc[8][4];
#pragma unroll
        for (int nt = 0; nt < 8; nt++)
#pragma unroll
            for (int r = 0; r < 4; r++) acc[nt][r] = 0.0f;

#pragma unroll
        for (int ks = 0; ks < 8; ++ks) {
            int a0i = (wm + g) * AQ_STR + ks * 8 + tig;
            uint32_t ah0 = Qh[a0i], ah1 = Qh[a0i + 8 * AQ_STR];
            uint32_t ah2 = Qh[a0i + 4], ah3 = Qh[a0i + 8 * AQ_STR + 4];
            uint32_t al0 = Ql[a0i], al1 = Ql[a0i + 8 * AQ_STR];
            uint32_t al2 = Ql[a0i + 4], al3 = Ql[a0i + 8 * AQ_STR + 4];
#pragma unroll
            for (int nt = 0; nt < 8; ++nt) {
                int b0i = (ks * 8 + tig) * KS_STR + nt * 8 + g;
                int b1i = b0i + 4 * KS_STR;
                uint32_t bh0 = Kh[b0i], bh1 = Kh[b1i];
                uint32_t bl0 = Kl[b0i], bl1 = Kl[b1i];
                mma16816(acc[nt], ah0, ah1, ah2, ah3, bh0, bh1);
                mma16816(acc[nt], ah0, ah1, ah2, ah3, bl0, bl1);
                mma16816(acc[nt], al0, al1, al2, al3, bh0, bh1);
            }
        }

        const int kbase = j * BLKQ;
#pragma unroll
        for (int nt = 0; nt < 8; ++nt) {
            int c0 = kbase + nt * 8 + 2 * tig;
            if (c0 > qp0)     acc[nt][0] = -INFINITY;
            if (c0 + 1 > qp0) acc[nt][1] = -INFINITY;
            if (c0 > qp1)     acc[nt][2] = -INFINITY;
            if (c0 + 1 > qp1) acc[nt][3] = -INFINITY;
        }
        float rm0 = -INFINITY, rm1 = -INFINITY;
#pragma unroll
        for (int nt = 0; nt < 8; ++nt) {
            rm0 = fmaxf(rm0, fmaxf(acc[nt][0], acc[nt][1]));
            rm1 = fmaxf(rm1, fmaxf(acc[nt][2], acc[nt][3]));
        }
        rm0 = fmaxf(rm0, __shfl_xor_sync(0xffffffffu, rm0, 1));
        rm0 = fmaxf(rm0, __shfl_xor_sync(0xffffffffu, rm0, 2));
        rm1 = fmaxf(rm1, __shfl_xor_sync(0xffffffffu, rm1, 1));
        rm1 = fmaxf(rm1, __shfl_xor_sync(0xffffffffu, rm1, 2));

        float mn0 = fmaxf(m0, rm0), mn1 = fmaxf(m1, rm1);
        float al0f = exp2f(m0 - mn0), al1f = exp2f(m1 - mn1);
        m0 = mn0; m1 = mn1;

        float s0 = 0.0f, s1 = 0.0f;
#pragma unroll
        for (int nt = 0; nt < 8; ++nt) {
            acc[nt][0] = exp2f(acc[nt][0] - mn0);
            acc[nt][1] = exp2f(acc[nt][1] - mn0);
            acc[nt][2] = exp2f(acc[nt][2] - mn1);
            acc[nt][3] = exp2f(acc[nt][3] - mn1);
            s0 += acc[nt][0] + acc[nt][1];
            s1 += acc[nt][2] + acc[nt][3];
        }
        s0 += __shfl_xor_sync(0xffffffffu, s0, 1);
        s0 += __shfl_xor_sync(0xffffffffu, s0, 2);
        s1 += __shfl_xor_sync(0xffffffffu, s1, 1);
        s1 += __shfl_xor_sync(0xffffffffu, s1, 2);
        l0 = l0 * al0f + s0;
        l1 = l1 * al1f + s1;

#pragma unroll
        for (int nt = 0; nt < 16; ++nt) {
            O[nt][0] *= al0f; O[nt][1] *= al0f;
            O[nt][2] *= al1f; O[nt][3] *= al1f;
        }

        __syncthreads();
        for (int idx = t; idx < 32 * 128; idx += 128) {
            int c2 = idx >> 7;
            int dd = idx & 127;
            size_t base = (size_t)(j * BLKQ + 2 * c2) * QKVN + 2560 + kvh * DH + dd;
            float v0 = g_qkv[base];
            float v1 = g_qkv[base + QKVN];
            uint32_t H, L;
            split2(v0, v1, H, L);
            Vh[c2 * VS_STR + dd] = H;
            Vl[c2 * VS_STR + dd] = L;
        }
        __syncthreads();

#pragma unroll
        for (int kk = 0; kk < 4; ++kk) {
            uint32_t ah0, ah1, ah2, ah3, al0_, al1_, al2_, al3_;
            split2(acc[2 * kk][0],     acc[2 * kk][1],     ah0, al0_);
            split2(acc[2 * kk][2],     acc[2 * kk][3],     ah1, al1_);
            split2(acc[2 * kk + 1][0], acc[2 * kk + 1][1], ah2, al2_);
            split2(acc[2 * kk + 1][2], acc[2 * kk + 1][3], ah3, al3_);
#pragma unroll
            for (int nt = 0; nt < 16; ++nt) {
                int b0i = (kk * 8 + tig) * VS_STR + nt * 8 + g;
                int b1i = b0i + 4 * VS_STR;
                uint32_t bh0 = Vh[b0i], bh1 = Vh[b1i];
                uint32_t bl0 = Vl[b0i], bl1 = Vl[b1i];
                mma16816(O[nt], ah0, ah1, ah2, ah3, bh0, bh1);
                mma16816(O[nt], al0_, al1_, al2_, al3_, bh0, bh1);
                mma16816(O[nt], ah0, ah1, ah2, ah3, bl0, bl1);
            }
        }
    }

    float inv0 = 1.0f / l0, inv1 = 1.0f / l1;
    int row0 = i * BLKQ + wm + g;
    int row1 = row0 + 8;
#pragma unroll
    for (int nt = 0; nt < 16; ++nt) {
        int d0 = nt * 8 + 2 * tig;
        uint32_t H, L;
        split2(O[nt][0] * inv0, O[nt][1] * inv0, H, L);
        *(uint32_t*)&g_oa_hi[(size_t)row0 * HID + h * DH + d0] = H;
        *(uint32_t*)&g_oa_lo[(size_t)row0 * HID + h * DH + d0] = L;
        split2(O[nt][2] * inv1, O[nt][3] * inv1, H, L);
        *(uint32_t*)&g_oa_hi[(size_t)row1 * HID + h * DH + d0] = H;
        *(uint32_t*)&g_oa_lo[(size_t)row1 * HID + h * DH + d0] = L;
    }
}

// ---------------- launch ----------------
extern "C" void kernel_launch(void* const* d_in, const int* in_sizes, int n_in,
                              void* d_out, int out_size)
{
    const float* hs  = (const float*)d_in[0];
    const int*   pos = (const int*)d_in[1];
    const float* Wq  = (const float*)d_in[2];
    const float* Wk  = (const float*)d_in[3];
    const float* Wv  = (const float*)d_in[4];
    const float* Wo  = (const float*)d_in[5];
    const float* Hm  = (const float*)d_in[6];
    float* out = (float*)d_out;

    float *qkv, *Sq, *Sk;
    __half *ha_hi, *ha_lo, *oa_hi, *oa_lo;
    __half2 *wb_hi, *wb_lo, *wob_hi, *wob_lo;
    cudaGetSymbolAddress((void**)&qkv,    g_qkv);
    cudaGetSymbolAddress((void**)&Sq,     g_Sq);
    cudaGetSymbolAddress((void**)&Sk,     g_Sk);
    cudaGetSymbolAddress((void**)&ha_hi,  g_ha_hi);
    cudaGetSymbolAddress((void**)&ha_lo,  g_ha_lo);
    cudaGetSymbolAddress((void**)&oa_hi,  g_oa_hi);
    cudaGetSymbolAddress((void**)&oa_lo,  g_oa_lo);
    cudaGetSymbolAddress((void**)&wb_hi,  g_wb_hi);
    cudaGetSymbolAddress((void**)&wb_lo,  g_wb_lo);
    cudaGetSymbolAddress((void**)&wob_hi, g_wob_hi);
    cudaGetSymbolAddress((void**)&wob_lo, g_wob_lo);

    cudaFuncSetAttribute(gemm_fp16_kernel<3>, cudaFuncAttributeMaxDynamicSharedMemorySize,
                         GEMM_SMEM_BYTES);
    cudaFuncSetAttribute(gemm_fp16_kernel<2>, cudaFuncAttributeMaxDynamicSharedMemorySize,
                         GEMM_SMEM_BYTES);
    cudaFuncSetAttribute(attn_kernel, cudaFuncAttributeMaxDynamicSharedMemorySize,
                         ATT_SMEM_BYTES);

    // operand prep
    split_a_kernel<<<SEQ * HID / 256, 256>>>(hs);
    pack_split_w_kernel<<<dim3(QKVN / 256, HID / 2), 256>>>(Wq, Wk, Wv);
    split_wo_kernel<<<dim3(HID / 256, HID / 2), 256>>>(Wo);

    // fused QKV projection (3-pass: feeds top-k selection, keep fp32-accurate)
    gemm_fp16_kernel<3><<<dim3(QKVN / 128, SEQ / 128), 256, GEMM_SMEM_BYTES>>>(
        ha_hi, ha_lo, wb_hi, wb_lo, qkv, SEQ, QKVN, HID);

    // RoPE
    invf_kernel<<<1, 64>>>();
    rope_table_kernel<<<SEQ, 64>>>(pos);
    rope_kernel<<<dim3(SEQ, NH), DH>>>(qkv, QKVN);
    rope_kernel<<<dim3(SEQ, NKV), DH>>>(qkv + 2048, QKVN);

    // sketches
    sketch_kernel<<<dim3(NBLK, NH), DH>>>(qkv, Hm, Sq, QKVN);
    sketch_kernel<<<dim3(NBLK, NKV), DH>>>(qkv + 2048, Hm, Sk, QKVN);

    // block scores + top-k
    topk_kernel<<<dim3(NBLK, NH), 64>>>();

    // sparse attention (tensor-core, emits fp16 split planes)
    attn_kernel<<<dim3(NBLK, NH), 128, ATT_SMEM_BYTES>>>();

    // output projection (2-pass: downstream of selection, ~3e-4 error budget)
    gemm_fp16_kernel<2><<<dim3(HID / 128, SEQ / 128), 256, GEMM_SMEM_BYTES>>>(
        oa_hi, oa_lo, wob_hi, wob_lo, out, SEQ, HID, HID);
}

// round 15
// speedup vs baseline: 1.3868x; 1.0200x over previous
#include <cuda_runtime.h>
#include <cuda_fp16.h>
#include <math.h>
#include <stdint.h>

// ---------------- problem constants ----------------
#define SEQ   4096
#define HID   2048
#define NH    16
#define NKV   4
#define DH    128
#define BLKQ  64
#define NBLK  64
#define MSK   32
#define KTOP  8
#define QKVN  3072          // fused QKV output columns (2048 q | 512 k | 512 v)

#define NEGV  (-1000000000.0f)

// ---------------- scratch (device globals; no allocation allowed) ----------------
__device__ float  g_qkv[SEQ * QKVN];         // fused q|k|v fp32, layout [s][3072]
__device__ __half g_ha_hi[SEQ * HID];        // hidden_states hi plane [s][k]
__device__ __half g_ha_lo[SEQ * HID];        // hidden_states lo plane
__device__ __half2 g_wb_hi[(HID/2) * QKVN];  // packed W_qkv hi, k-pair interleaved [k2][n]
__device__ __half2 g_wb_lo[(HID/2) * QKVN];
__device__ __half g_oa_hi[SEQ * HID];        // attention-out hi plane [s][n]
__device__ __half g_oa_lo[SEQ * HID];
__device__ __half2 g_wob_hi[(HID/2) * HID];  // Wo hi, k-pair interleaved [k2][n]
__device__ __half2 g_wob_lo[(HID/2) * HID];
__device__ float  g_Sq[NH * NBLK * MSK];
__device__ float  g_Sk[NKV * NBLK * MSK];
__device__ int    g_topk[NH * NBLK * KTOP];
__device__ float  g_cos[SEQ * 64];
__device__ float  g_sin[SEQ * 64];
__device__ double g_invf[64];

// ---------------- common fp16 helpers ----------------
__device__ __forceinline__ uint32_t smem_u32(const void* p) {
    uint32_t a;
    asm("{ .reg .u64 t; cvta.to.shared.u64 t, %1; cvt.u32.u64 %0, t; }" : "=r"(a) : "l"(p));
    return a;
}
__device__ __forceinline__ void mma16816(float c[4],
    uint32_t a0, uint32_t a1, uint32_t a2, uint32_t a3, uint32_t b0, uint32_t b1)
{
    asm volatile(
        "mma.sync.aligned.m16n8k16.row.col.f32.f16.f16.f32 "
        "{%0,%1,%2,%3}, {%4,%5,%6,%7}, {%8,%9}, {%0,%1,%2,%3};"
        : "+f"(c[0]), "+f"(c[1]), "+f"(c[2]), "+f"(c[3])
        : "r"(a0), "r"(a1), "r"(a2), "r"(a3), "r"(b0), "r"(b1));
}
__device__ __forceinline__ void split2(float x, float y, uint32_t& H, uint32_t& L) {
    __half hx = __float2half_rn(x), hy = __float2half_rn(y);
    __half2 hh = __halves2half2(hx, hy);
    H = *(uint32_t*)&hh;
    __half2 ll = __halves2half2(__float2half_rn(x - __half2float(hx)),
                                __float2half_rn(y - __half2float(hy)));
    L = *(uint32_t*)&ll;
}

// =======================================================================
// fp16 split GEMM: C[M,N] = A[M,K] @ B[K,N]
// A planes row-major fp16 [M][K]; B planes half2 k-pair interleaved [K/2][N].
// CTA 128x128, BK=32, 256 threads, warp tile 64x32.
// 3-stage cp.async ring, ONE __syncthreads per iteration.
// PASSES=3: hh + h*l + l*h (~fp32).  PASSES=2: hh + h*l (A-lo never touched).
// =======================================================================
#define A_STR2 20
#define B_STR2 136
#define A_PLANE_W (128 * A_STR2)
#define B_PLANE_W (16 * B_STR2)
#define STAGE_W   (2 * A_PLANE_W + 2 * B_PLANE_W)   // 9472 words = 37888 B
#define NSTG 3
#define GEMM_SMEM_BYTES (NSTG * STAGE_W * 4)        // 113664 B

#define CP16(dst, src) \
    asm volatile("cp.async.cg.shared.global [%0], [%1], 16;" :: "r"(dst), "l"(src))
#define CP_COMMIT() asm volatile("cp.async.commit_group;")
#define CP_WAIT1()  asm volatile("cp.async.wait_group 1;")

template <int PASSES>
__global__ __launch_bounds__(256, 2) void gemm_fp16_kernel(
    const __half* __restrict__ Ah, const __half* __restrict__ Al,
    const __half2* __restrict__ Bh, const __half2* __restrict__ Bl,
    float* __restrict__ C, int M, int N, int K)
{
    extern __shared__ uint32_t smw[];
    const uint32_t smb = smem_u32(smw);

    const int bx = blockIdx.x * 128;
    const int by = blockIdx.y * 128;
    const int tid  = threadIdx.x;
    const int warp = tid >> 5;
    const int lane = tid & 31;
    const int g    = lane >> 2;
    const int tig  = lane & 3;
    const int warp_m = (warp & 1) * 64;
    const int warp_n = (warp >> 1) * 32;

    const int NIT = K / 32;
    const int ar = tid >> 2;
    const int ac = (tid & 3) * 16;
    const int bk = tid >> 5;
    const int bn = (tid & 31) * 16;

    auto load_stage = [&](int it, int s) {
        const int kt = it * 32;
        const uint32_t base = smb + (uint32_t)s * (STAGE_W * 4);
        {
            const char* sh = (const char*)(Ah + (size_t)(by + ar) * K + kt);
            CP16(base + ar * 80 + ac, sh + ac);
            const char* sh2 = (const char*)(Ah + (size_t)(by + ar + 64) * K + kt);
            CP16(base + (ar + 64) * 80 + ac, sh2 + ac);
            if (PASSES == 3) {
                const char* sl = (const char*)(Al + (size_t)(by + ar) * K + kt);
                CP16(base + A_PLANE_W * 4 + ar * 80 + ac, sl + ac);
                const char* sl2 = (const char*)(Al + (size_t)(by + ar + 64) * K + kt);
                CP16(base + A_PLANE_W * 4 + (ar + 64) * 80 + ac, sl2 + ac);
            }
        }
        {
            const uint32_t bb = base + 2 * A_PLANE_W * 4;
            const char* sh = (const char*)(Bh + (size_t)(kt / 2 + bk) * N + bx);
            const char* sl = (const char*)(Bl + (size_t)(kt / 2 + bk) * N + bx);
            CP16(bb + bk * 544 + bn, sh + bn);
            CP16(bb + B_PLANE_W * 4 + bk * 544 + bn, sl + bn);
            const char* sh2 = (const char*)(Bh + (size_t)(kt / 2 + bk + 8) * N + bx);
            const char* sl2 = (const char*)(Bl + (size_t)(kt / 2 + bk + 8) * N + bx);
            CP16(bb + (bk + 8) * 544 + bn, sh2 + bn);
            CP16(bb + B_PLANE_W * 4 + (bk + 8) * 544 + bn, sl2 + bn);
        }
    };

    float acc[4][4][4];
#pragma unroll
    for (int mt = 0; mt < 4; mt++)
#pragma unroll
        for (int nt = 0; nt < 4; nt++)
#pragma unroll
            for (int r = 0; r < 4; r++) acc[mt][nt][r] = 0.0f;

    load_stage(0, 0); CP_COMMIT();
    load_stage(1, 1); CP_COMMIT();

    int slot = 2;         // next ring slot to fill (stage it+2 at iter it)
    for (int it = 0; it < NIT; ++it) {
        CP_WAIT1();           // pending = {it, it+1} -> stage it complete
        __syncthreads();      // data visible; all warps done with stage it-1

        // fill the slot freed at iter it-1 (ring position (it+2) % 3)
        if (it + 2 < NIT) {
            load_stage(it + 2, slot);
            CP_COMMIT();
        }

        const uint32_t* st = smw + (it % NSTG) * STAGE_W;
        const uint32_t* AH = st;
        const uint32_t* AL = st + A_PLANE_W;
        const uint32_t* BH = st + 2 * A_PLANE_W;
        const uint32_t* BL = BH + B_PLANE_W;

#pragma unroll
        for (int kk = 0; kk < 2; ++kk) {
            uint32_t a[4][4], al2[4][4], bh[4][2], bl[4][2];
#pragma unroll
            for (int nt = 0; nt < 4; nt++) {
                int n = warp_n + nt * 8 + g;
                bh[nt][0] = BH[(kk * 8 + tig) * B_STR2 + n];
                bh[nt][1] = BH[(kk * 8 + tig + 4) * B_STR2 + n];
                bl[nt][0] = BL[(kk * 8 + tig) * B_STR2 + n];
                bl[nt][1] = BL[(kk * 8 + tig + 4) * B_STR2 + n];
            }
#pragma unroll
            for (int mt = 0; mt < 4; mt++) {
                int row = warp_m + mt * 16 + g;
                a[mt][0] = AH[row * A_STR2 + kk * 8 + tig];
                a[mt][1] = AH[(row + 8) * A_STR2 + kk * 8 + tig];
                a[mt][2] = AH[row * A_STR2 + kk * 8 + tig + 4];
                a[mt][3] = AH[(row + 8) * A_STR2 + kk * 8 + tig + 4];
            }
            if (PASSES == 3) {
                // hoist A-lo loads: in flight during passes 1-2
#pragma unroll
                for (int mt = 0; mt < 4; mt++) {
                    int row = warp_m + mt * 16 + g;
                    al2[mt][0] = AL[row * A_STR2 + kk * 8 + tig];
                    al2[mt][1] = AL[(row + 8) * A_STR2 + kk * 8 + tig];
                    al2[mt][2] = AL[row * A_STR2 + kk * 8 + tig + 4];
                    al2[mt][3] = AL[(row + 8) * A_STR2 + kk * 8 + tig + 4];
                }
            }
            // pass 1: hi * hi
#pragma unroll
            for (int mt = 0; mt < 4; mt++)
#pragma unroll
                for (int nt = 0; nt < 4; nt++)
                    mma16816(acc[mt][nt], a[mt][0], a[mt][1], a[mt][2], a[mt][3],
                             bh[nt][0], bh[nt][1]);
            // pass 2: hi * lo
#pragma unroll
            for (int mt = 0; mt < 4; mt++)
#pragma unroll
                for (int nt = 0; nt < 4; nt++)
                    mma16816(acc[mt][nt], a[mt][0], a[mt][1], a[mt][2], a[mt][3],
                             bl[nt][0], bl[nt][1]);
            if (PASSES == 3) {
                // pass 3: lo * hi
#pragma unroll
                for (int mt = 0; mt < 4; mt++)
#pragma unroll
                    for (int nt = 0; nt < 4; nt++)
                        mma16816(acc[mt][nt], al2[mt][0], al2[mt][1], al2[mt][2], al2[mt][3],
                                 bh[nt][0], bh[nt][1]);
            }
        }
        if (++slot == NSTG) slot = 0;
    }

#pragma unroll
    for (int mt = 0; mt < 4; mt++) {
#pragma unroll
        for (int nt = 0; nt < 4; nt++) {
            int row = by + warp_m + mt * 16 + g;
            int col = bx + warp_n + nt * 8 + 2 * tig;
            *(float2*)&C[(size_t)row * N + col]       = make_float2(acc[mt][nt][0], acc[mt][nt][1]);
            *(float2*)&C[(size_t)(row + 8) * N + col] = make_float2(acc[mt][nt][2], acc[mt][nt][3]);
        }
    }
}

// ---------------- operand prep kernels ----------------
__global__ void split_a_kernel(const float* __restrict__ src)
{
    int i = blockIdx.x * 256 + threadIdx.x;
    float x = src[i];
    __half h = __float2half_rn(x);
    g_ha_hi[i] = h;
    g_ha_lo[i] = __float2half_rn(x - __half2float(h));
}

__global__ void pack_split_w_kernel(const float* __restrict__ Wq,
                                    const float* __restrict__ Wk,
                                    const float* __restrict__ Wv)
{
    int k2 = blockIdx.y;
    int j  = blockIdx.x * 256 + threadIdx.x;
    const float* W; int col, width;
    if (j < 2048)      { W = Wq; col = j;        width = 2048; }
    else if (j < 2560) { W = Wk; col = j - 2048; width = 512;  }
    else               { W = Wv; col = j - 2560; width = 512;  }
    float x0 = W[(size_t)(2 * k2) * width + col];
    float x1 = W[(size_t)(2 * k2 + 1) * width + col];
    uint32_t H, L;
    split2(x0, x1, H, L);
    g_wb_hi[(size_t)k2 * QKVN + j] = *(__half2*)&H;
    g_wb_lo[(size_t)k2 * QKVN + j] = *(__half2*)&L;
}

__global__ void split_wo_kernel(const float* __restrict__ Wo)
{
    int k2 = blockIdx.y;
    int n  = blockIdx.x * 256 + threadIdx.x;
    float x0 = Wo[(size_t)(2 * k2) * HID + n];
    float x1 = Wo[(size_t)(2 * k2 + 1) * HID + n];
    uint32_t H, L;
    split2(x0, x1, H, L);
    g_wob_hi[(size_t)k2 * HID + n] = *(__half2*)&H;
    g_wob_lo[(size_t)k2 * HID + n] = *(__half2*)&L;
}

// ---------------- RoPE tables ----------------
__global__ void invf_kernel()
{
    int j = threadIdx.x;
    g_invf[j] = pow(10000.0, -(double)(2 * j) / 128.0);
}

__global__ void rope_table_kernel(const int* __restrict__ pos)
{
    int s = blockIdx.x;
    int j = threadIdx.x;
    double ang = (double)pos[s] * g_invf[j];
    double r = fmod(ang, 6.283185307179586476925286766559);
    float sv, cv;
    sincosf((float)r, &sv, &cv);
    g_cos[s * 64 + j] = cv;
    g_sin[s * 64 + j] = sv;
}

__global__ void rope_kernel(float* __restrict__ buf, int stride)
{
    int s = blockIdx.x;
    int h = blockIdx.y;
    int d = threadIdx.x;
    __shared__ float row[DH];
    float x = buf[(size_t)s * stride + h * DH + d];
    row[d] = x;
    __syncthreads();
    float part = (d < 64) ? -row[d + 64] : row[d - 64];
    float c  = g_cos[s * 64 + (d & 63)];
    float sn = g_sin[s * 64 + (d & 63)];
    buf[(size_t)s * stride + h * DH + d] = x * c + part * sn;
}

// ---------------- sketch ----------------
__global__ void sketch_kernel(const float* __restrict__ buf, const float* __restrict__ Hm,
                              float* __restrict__ Sout, int stride)
{
    int n = blockIdx.x;
    int h = blockIdx.y;
    int d = threadIdx.x;
    __shared__ float mv[DH];
    float sum = 0.0f;
#pragma unroll 8
    for (int r = 0; r < BLKQ; r++)
        sum += buf[(size_t)(n * BLKQ + r) * stride + h * DH + d];
    mv[d] = sum * (1.0f / 64.0f);
    __syncthreads();
    if (d < MSK) {
        float acc = 0.0f;
#pragma unroll 8
        for (int dd = 0; dd < DH; dd++)
            acc += mv[dd] * Hm[dd * MSK + d];
        Sout[(h * NBLK + n) * MSK + d] = acc;
    }
}

// ---------------- block-score + top-k ----------------
__global__ void topk_kernel()
{
    int i = blockIdx.x;
    int h = blockIdx.y;
    int j = threadIdx.x;
    __shared__ float bs[NBLK];

    float val;
    if (j > i) {
        val = NEGV;
    } else {
        const float* sq = &g_Sq[(h * NBLK + i) * MSK];
        const float* sk = &g_Sk[((h >> 2) * NBLK + j) * MSK];
        float acc = 0.0f;
#pragma unroll
        for (int m = 0; m < MSK; m++) acc += sq[m] * sk[m];
        val = acc;
    }
    if (j == i) val = 1000000000.0f;
    bs[j] = val;
    __syncthreads();

    if (j == 0) {
        for (int t = 0; t < KTOP; t++) {
            float best = -INFINITY;
            int bi = 0;
            for (int c = 0; c < NBLK; c++) {
                if (bs[c] > best) { best = bs[c]; bi = c; }
            }
            g_topk[(h * NBLK + i) * KTOP + t] = bi;
            bs[bi] = -INFINITY;
        }
    }
}

// =======================================================================
// sparse flash attention via m16n8k16 HMMA (unchanged, verified)
// =======================================================================
#define AQ_STR 68
#define KS_STR 73
#define VS_STR 136
#define Q_PLANE (64 * AQ_STR)
#define K_PLANE (64 * KS_STR)
#define V_PLANE (32 * VS_STR)
#define ATT_SMEM_W (2 * Q_PLANE + 2 * K_PLANE)
#define ATT_SMEM_BYTES (ATT_SMEM_W * 4)

__global__ __launch_bounds__(128) void attn_kernel()
{
    extern __shared__ uint32_t smw[];
    uint32_t* Qh = smw;
    uint32_t* Ql = smw + Q_PLANE;
    uint32_t* Kh = smw + 2 * Q_PLANE;
    uint32_t* Kl = Kh + K_PLANE;
    uint32_t* Vh = Kh;
    uint32_t* Vl = Kh + V_PLANE;

    const int i   = blockIdx.x;
    const int h   = blockIdx.y;
    const int kvh = h >> 2;
    const int t    = threadIdx.x;
    const int warp = t >> 5;
    const int lane = t & 31;
    const int g    = lane >> 2;
    const int tig  = lane & 3;
    const int wm   = warp * 16;

    const float QSCALE = 0.12753100795667498f;  // 1/sqrt(128) * log2(e)

    for (int idx = t; idx < 64 * 64; idx += 128) {
        int r  = idx >> 6;
        int k2 = idx & 63;
        float2 q = *(const float2*)&g_qkv[(size_t)(i * BLKQ + r) * QKVN + h * DH + 2 * k2];
        uint32_t H, L;
        split2(q.x * QSCALE, q.y * QSCALE, H, L);
        Qh[r * AQ_STR + k2] = H;
        Ql[r * AQ_STR + k2] = L;
    }

    float O[16][4];
#pragma unroll
    for (int nt = 0; nt < 16; nt++)
#pragma unroll
        for (int r = 0; r < 4; r++) O[nt][r] = 0.0f;

    float m0 = -INFINITY, m1 = -INFINITY, l0 = 0.0f, l1 = 0.0f;
    const int qp0 = i * BLKQ + wm + g;
    const int qp1 = qp0 + 8;

    for (int kb = 0; kb < KTOP; kb++) {
        const int j = g_topk[(h * NBLK + i) * KTOP + kb];

        __syncthreads();
        for (int idx = t; idx < 64 * 64; idx += 128) {
            int c  = idx >> 6;
            int d2 = idx & 63;
            float2 kv = *(const float2*)&g_qkv[(size_t)(j * BLKQ + c) * QKVN + 2048 + kvh * DH + 2 * d2];
            uint32_t H, L;
            split2(kv.x, kv.y, H, L);
            Kh[d2 * KS_STR + c] = H;
            Kl[d2 * KS_STR + c] = L;
        }
        __syncthreads();

        float acc[8][4];
#pragma unroll
        for (int nt = 0; nt < 8; nt++)
#pragma unroll
            for (int r = 0; r < 4; r++) acc[nt][r] = 0.0f;

#pragma unroll
        for (int ks = 0; ks < 8; ++ks) {
            int a0i = (wm + g) * AQ_STR + ks * 8 + tig;
            uint32_t ah0 = Qh[a0i], ah1 = Qh[a0i + 8 * AQ_STR];
            uint32_t ah2 = Qh[a0i + 4], ah3 = Qh[a0i + 8 * AQ_STR + 4];
            uint32_t al0 = Ql[a0i], al1 = Ql[a0i + 8 * AQ_STR];
            uint32_t al2 = Ql[a0i + 4], al3 = Ql[a0i + 8 * AQ_STR + 4];
#pragma unroll
            for (int nt = 0; nt < 8; ++nt) {
                int b0i = (ks * 8 + tig) * KS_STR + nt * 8 + g;
                int b1i = b0i + 4 * KS_STR;
                uint32_t bh0 = Kh[b0i], bh1 = Kh[b1i];
                uint32_t bl0 = Kl[b0i], bl1 = Kl[b1i];
                mma16816(acc[nt], ah0, ah1, ah2, ah3, bh0, bh1);
                mma16816(acc[nt], ah0, ah1, ah2, ah3, bl0, bl1);
                mma16816(acc[nt], al0, al1, al2, al3, bh0, bh1);
            }
        }

        const int kbase = j * BLKQ;
#pragma unroll
        for (int nt = 0; nt < 8; ++nt) {
            int c0 = kbase + nt * 8 + 2 * tig;
            if (c0 > qp0)     acc[nt][0] = -INFINITY;
            if (c0 + 1 > qp0) acc[nt][1] = -INFINITY;
            if (c0 > qp1)     acc[nt][2] = -INFINITY;
            if (c0 + 1 > qp1) acc[nt][3] = -INFINITY;
        }
        float rm0 = -INFINITY, rm1 = -INFINITY;
#pragma unroll
        for (int nt = 0; nt < 8; ++nt) {
            rm0 = fmaxf(rm0, fmaxf(acc[nt][0], acc[nt][1]));
            rm1 = fmaxf(rm1, fmaxf(acc[nt][2], acc[nt][3]));
        }
        rm0 = fmaxf(rm0, __shfl_xor_sync(0xffffffffu, rm0, 1));
        rm0 = fmaxf(rm0, __shfl_xor_sync(0xffffffffu, rm0, 2));
        rm1 = fmaxf(rm1, __shfl_xor_sync(0xffffffffu, rm1, 1));
        rm1 = fmaxf(rm1, __shfl_xor_sync(0xffffffffu, rm1, 2));

        float mn0 = fmaxf(m0, rm0), mn1 = fmaxf(m1, rm1);
        float al0f = exp2f(m0 - mn0), al1f = exp2f(m1 - mn1);
        m0 = mn0; m1 = mn1;

        float s0 = 0.0f, s1 = 0.0f;
#pragma unroll
        for (int nt = 0; nt < 8; ++nt) {
            acc[nt][0] = exp2f(acc[nt][0] - mn0);
            acc[nt][1] = exp2f(acc[nt][1] - mn0);
            acc[nt][2] = exp2f(acc[nt][2] - mn1);
            acc[nt][3] = exp2f(acc[nt][3] - mn1);
            s0 += acc[nt][0] + acc[nt][1];
            s1 += acc[nt][2] + acc[nt][3];
        }
        s0 += __shfl_xor_sync(0xffffffffu, s0, 1);
        s0 += __shfl_xor_sync(0xffffffffu, s0, 2);
        s1 += __shfl_xor_sync(0xffffffffu, s1, 1);
        s1 += __shfl_xor_sync(0xffffffffu, s1, 2);
        l0 = l0 * al0f + s0;
        l1 = l1 * al1f + s1;

#pragma unroll
        for (int nt = 0; nt < 16; ++nt) {
            O[nt][0] *= al0f; O[nt][1] *= al0f;
            O[nt][2] *= al1f; O[nt][3] *= al1f;
        }

        __syncthreads();
        for (int idx = t; idx < 32 * 128; idx += 128) {
            int c2 = idx >> 7;
            int dd = idx & 127;
            size_t base = (size_t)(j * BLKQ + 2 * c2) * QKVN + 2560 + kvh * DH + dd;
            float v0 = g_qkv[base];
            float v1 = g_qkv[base + QKVN];
            uint32_t H, L;
            split2(v0, v1, H, L);
            Vh[c2 * VS_STR + dd] = H;
            Vl[c2 * VS_STR + dd] = L;
        }
        __syncthreads();

#pragma unroll
        for (int kk = 0; kk < 4; ++kk) {
            uint32_t ah0, ah1, ah2, ah3, al0_, al1_, al2_, al3_;
            split2(acc[2 * kk][0],     acc[2 * kk][1],     ah0, al0_);
            split2(acc[2 * kk][2],     acc[2 * kk][3],     ah1, al1_);
            split2(acc[2 * kk + 1][0], acc[2 * kk + 1][1], ah2, al2_);
            split2(acc[2 * kk + 1][2], acc[2 * kk + 1][3], ah3, al3_);
#pragma unroll
            for (int nt = 0; nt < 16; ++nt) {
                int b0i = (kk * 8 + tig) * VS_STR + nt * 8 + g;
                int b1i = b0i + 4 * VS_STR;
                uint32_t bh0 = Vh[b0i], bh1 = Vh[b1i];
                uint32_t bl0 = Vl[b0i], bl1 = Vl[b1i];
                mma16816(O[nt], ah0, ah1, ah2, ah3, bh0, bh1);
                mma16816(O[nt], al0_, al1_, al2_, al3_, bh0, bh1);
                mma16816(O[nt], ah0, ah1, ah2, ah3, bl0, bl1);
            }
        }
    }

    float inv0 = 1.0f / l0, inv1 = 1.0f / l1;
    int row0 = i * BLKQ + wm + g;
    int row1 = row0 + 8;
#pragma unroll
    for (int nt = 0; nt < 16; ++nt) {
        int d0 = nt * 8 + 2 * tig;
        uint32_t H, L;
        split2(O[nt][0] * inv0, O[nt][1] * inv0, H, L);
        *(uint32_t*)&g_oa_hi[(size_t)row0 * HID + h * DH + d0] = H;
        *(uint32_t*)&g_oa_lo[(size_t)row0 * HID + h * DH + d0] = L;
        split2(O[nt][2] * inv1, O[nt][3] * inv1, H, L);
        *(uint32_t*)&g_oa_hi[(size_t)row1 * HID + h * DH + d0] = H;
        *(uint32_t*)&g_oa_lo[(size_t)row1 * HID + h * DH + d0] = L;
    }
}

// ---------------- launch ----------------
extern "C" void kernel_launch(void* const* d_in, const int* in_sizes, int n_in,
                              void* d_out, int out_size)
{
    const float* hs  = (const float*)d_in[0];
    const int*   pos = (const int*)d_in[1];
    const float* Wq  = (const float*)d_in[2];
    const float* Wk  = (const float*)d_in[3];
    const float* Wv  = (const float*)d_in[4];
    const float* Wo  = (const float*)d_in[5];
    const float* Hm  = (const float*)d_in[6];
    float* out = (float*)d_out;

    float *qkv, *Sq, *Sk;
    __half *ha_hi, *ha_lo, *oa_hi, *oa_lo;
    __half2 *wb_hi, *wb_lo, *wob_hi, *wob_lo;
    cudaGetSymbolAddress((void**)&qkv,    g_qkv);
    cudaGetSymbolAddress((void**)&Sq,     g_Sq);
    cudaGetSymbolAddress((void**)&Sk,     g_Sk);
    cudaGetSymbolAddress((void**)&ha_hi,  g_ha_hi);
    cudaGetSymbolAddress((void**)&ha_lo,  g_ha_lo);
    cudaGetSymbolAddress((void**)&oa_hi,  g_oa_hi);
    cudaGetSymbolAddress((void**)&oa_lo,  g_oa_lo);
    cudaGetSymbolAddress((void**)&wb_hi,  g_wb_hi);
    cudaGetSymbolAddress((void**)&wb_lo,  g_wb_lo);
    cudaGetSymbolAddress((void**)&wob_hi, g_wob_hi);
    cudaGetSymbolAddress((void**)&wob_lo, g_wob_lo);

    cudaFuncSetAttribute(gemm_fp16_kernel<3>, cudaFuncAttributeMaxDynamicSharedMemorySize,
                         GEMM_SMEM_BYTES);
    cudaFuncSetAttribute(gemm_fp16_kernel<2>, cudaFuncAttributeMaxDynamicSharedMemorySize,
                         GEMM_SMEM_BYTES);
    cudaFuncSetAttribute(attn_kernel, cudaFuncAttributeMaxDynamicSharedMemorySize,
                         ATT_SMEM_BYTES);

    // operand prep
    split_a_kernel<<<SEQ * HID / 256, 256>>>(hs);
    pack_split_w_kernel<<<dim3(QKVN / 256, HID / 2), 256>>>(Wq, Wk, Wv);
    split_wo_kernel<<<dim3(HID / 256, HID / 2), 256>>>(Wo);

    // fused QKV projection (3-pass: feeds top-k selection, keep fp32-accurate)
    gemm_fp16_kernel<3><<<dim3(QKVN / 128, SEQ / 128), 256, GEMM_SMEM_BYTES>>>(
        ha_hi, ha_lo, wb_hi, wb_lo, qkv, SEQ, QKVN, HID);

    // RoPE
    invf_kernel<<<1, 64>>>();
    rope_table_kernel<<<SEQ, 64>>>(pos);
    rope_kernel<<<dim3(SEQ, NH), DH>>>(qkv, QKVN);
    rope_kernel<<<dim3(SEQ, NKV), DH>>>(qkv + 2048, QKVN);

    // sketches
    sketch_kernel<<<dim3(NBLK, NH), DH>>>(qkv, Hm, Sq, QKVN);
    sketch_kernel<<<dim3(NBLK, NKV), DH>>>(qkv + 2048, Hm, Sk, QKVN);

    // block scores + top-k
    topk_kernel<<<dim3(NBLK, NH), 64>>>();

    // sparse attention (tensor-core, emits fp16 split planes)
    attn_kernel<<<dim3(NBLK, NH), 128, ATT_SMEM_BYTES>>>();

    // output projection (2-pass: downstream of selection, ~3e-4 error budget)
    gemm_fp16_kernel<2><<<dim3(HID / 128, SEQ / 128), 256, GEMM_SMEM_BYTES>>>(
        oa_hi, oa_lo, wob_hi, wob_lo, out, SEQ, HID, HID);
}